// round 4
// baseline (speedup 1.0000x reference)
#include <cuda_runtime.h>
#include <cstdint>
#include <cstddef>
#include <math.h>

#define SEQ   2048
#define BATCH 8
#define DIN   1024
#define DQK   128
#define NG    32

#define SQt 128   // queries per attention block
#define SKt 64    // keys per tile
#define QTS 132   // Qt row stride (d-major)
#define KTS 68    // Kt row stride (d-major)
#define VS_ 132   // Vs / Pt row stride

#define NEG_INF (__int_as_float(0xff800000))

// Scratch for projected Q, K, V (device globals: no allocation allowed)
__device__ float g_proj[3][(size_t)BATCH * SEQ * DQK];

struct InArgs { const float* X[3]; const float* W[3]; const float* B[3]; };
struct GIdx   { int g[NG]; };

// ---------------------------------------------------------------------------
// Projection GEMM: Out[m, j] = sum_d X[m, d] * W[j, d] + b[j]
// M = 16384, N = 128, K = 1024.  BM=128, BN=128, BK=8, 256 threads, 8x8/thread.
// ---------------------------------------------------------------------------
__global__ __launch_bounds__(256) void proj_kernel(InArgs in) {
    const int which = blockIdx.y;
    const float* __restrict__ X    = in.X[which];
    const float* __restrict__ W    = in.W[which];
    const float* __restrict__ bias = in.B[which];
    float* __restrict__ Out = g_proj[which];

    const int M0 = blockIdx.x * 128;
    __shared__ float As[8][128];
    __shared__ float Bs[8][128];

    const int tid = threadIdx.x;
    const int ty = tid >> 4, tx = tid & 15;
    const int lr = tid >> 1;          // 0..127
    const int lc = (tid & 1) * 4;     // 0 or 4

    float acc[8][8];
#pragma unroll
    for (int i = 0; i < 8; i++)
#pragma unroll
        for (int j = 0; j < 8; j++) acc[i][j] = 0.f;

    const float* Xp = X + (size_t)(M0 + lr) * DIN + lc;
    const float* Wp = W + (size_t)lr * DIN + lc;

    for (int k0 = 0; k0 < DIN; k0 += 8) {
        float4 av = *(const float4*)(Xp + k0);
        float4 bv = *(const float4*)(Wp + k0);
        As[lc + 0][lr] = av.x; As[lc + 1][lr] = av.y;
        As[lc + 2][lr] = av.z; As[lc + 3][lr] = av.w;
        Bs[lc + 0][lr] = bv.x; Bs[lc + 1][lr] = bv.y;
        Bs[lc + 2][lr] = bv.z; Bs[lc + 3][lr] = bv.w;
        __syncthreads();
#pragma unroll
        for (int kk = 0; kk < 8; kk++) {
            float a[8], b[8];
            *(float4*)(a)     = *(const float4*)&As[kk][ty * 8];
            *(float4*)(a + 4) = *(const float4*)&As[kk][ty * 8 + 4];
            *(float4*)(b)     = *(const float4*)&Bs[kk][tx * 8];
            *(float4*)(b + 4) = *(const float4*)&Bs[kk][tx * 8 + 4];
#pragma unroll
            for (int i = 0; i < 8; i++)
#pragma unroll
                for (int j = 0; j < 8; j++)
                    acc[i][j] = fmaf(a[i], b[j], acc[i][j]);
        }
        __syncthreads();
    }

    float bb[8];
    *(float4*)(bb)     = *(const float4*)&bias[tx * 8];
    *(float4*)(bb + 4) = *(const float4*)&bias[tx * 8 + 4];
#pragma unroll
    for (int i = 0; i < 8; i++) {
        float4 o0 = make_float4(acc[i][0] + bb[0], acc[i][1] + bb[1],
                                acc[i][2] + bb[2], acc[i][3] + bb[3]);
        float4 o1 = make_float4(acc[i][4] + bb[4], acc[i][5] + bb[5],
                                acc[i][6] + bb[6], acc[i][7] + bb[7]);
        float* op = Out + (size_t)(M0 + ty * 8 + i) * DQK + tx * 8;
        *(float4*)op       = o0;
        *(float4*)(op + 4) = o1;
    }
}

// ---------------------------------------------------------------------------
// Flash-style attention with causal + global-token mask.
// Block: one (batch, 128-query tile). 256 threads = 16x16 grid.
// Thread owns S rows ty*8..+7, S cols tx*4..+3, O cols {c*16+tx : c in 0..7}.
// ---------------------------------------------------------------------------
__global__ __launch_bounds__(256) void attn_kernel(float* __restrict__ Out, GIdx gt) {
    extern __shared__ float sm[];
    float* Qt = sm;                     // [128 d][132]  (rows, scaled by 1/sqrt(dk))
    float* Kt = Qt + 128 * QTS;         // [128 d][68]
    float* Vs = Kt + 128 * KTS;         // [64 k][132]
    float* Pt = Vs + SKt * VS_;         // [64 k][132]  (P transposed: k-major)
    __shared__ unsigned gbm[SEQ / 32];

    const int b  = blockIdx.y;
    const int q0 = blockIdx.x * SQt;
    const int tid = threadIdx.x;
    const int ty = tid >> 4, tx = tid & 15;

    const float* Qb = g_proj[0] + (size_t)b * SEQ * DQK;
    const float* Kb = g_proj[1] + (size_t)b * SEQ * DQK;
    const float* Vb = g_proj[2] + (size_t)b * SEQ * DQK;

    if (tid < SEQ / 32) gbm[tid] = 0u;
    __syncthreads();
    if (tid < NG) { int g = gt.g[tid]; atomicOr(&gbm[g >> 5], 1u << (g & 31)); }

    const float inv_scale = 0.08838834764831845f;  // 1/sqrt(128)
    for (int i = tid; i < SQt * 32; i += 256) {
        int row = i >> 5; int d4 = (i & 31) << 2;
        float4 v = *(const float4*)(Qb + (size_t)(q0 + row) * DQK + d4);
        Qt[(d4 + 0) * QTS + row] = v.x * inv_scale;
        Qt[(d4 + 1) * QTS + row] = v.y * inv_scale;
        Qt[(d4 + 2) * QTS + row] = v.z * inv_scale;
        Qt[(d4 + 3) * QTS + row] = v.w * inv_scale;
    }
    __syncthreads();

    const unsigned qw = gbm[(q0 >> 5)] | gbm[(q0 >> 5) + 1] |
                        gbm[(q0 >> 5) + 2] | gbm[(q0 >> 5) + 3];
    const bool blockHasG = (qw != 0u);
    bool grow[8];
#pragma unroll
    for (int r = 0; r < 8; r++) {
        int q = q0 + ty * 8 + r;
        grow[r] = (gbm[q >> 5] >> (q & 31)) & 1u;
    }

    float m_i[8], l_i[8], o[8][8];
#pragma unroll
    for (int r = 0; r < 8; r++) {
        m_i[r] = NEG_INF; l_i[r] = 0.f;
#pragma unroll
        for (int c = 0; c < 8; c++) o[r][c] = 0.f;
    }

    for (int j = 0; j < SEQ / SKt; j++) {
        const int k0 = j * SKt;
        if (k0 > q0 + SQt - 1) {  // strictly-future tile: only globals matter
            if (!blockHasG && (gbm[k0 >> 5] | gbm[(k0 >> 5) + 1]) == 0u) continue;
        }
        __syncthreads();  // previous PV done: safe to overwrite Kt/Vs/Pt
        for (int i = tid; i < SKt * 32; i += 256) {
            int row = i >> 5; int d4 = (i & 31) << 2;
            float4 kv = *(const float4*)(Kb + (size_t)(k0 + row) * DQK + d4);
            Kt[(d4 + 0) * KTS + row] = kv.x;
            Kt[(d4 + 1) * KTS + row] = kv.y;
            Kt[(d4 + 2) * KTS + row] = kv.z;
            Kt[(d4 + 3) * KTS + row] = kv.w;
            float4 vv = *(const float4*)(Vb + (size_t)(k0 + row) * DQK + d4);
            *(float4*)&Vs[row * VS_ + d4] = vv;
        }
        __syncthreads();

        float s[8][4];
#pragma unroll
        for (int r = 0; r < 8; r++) { s[r][0] = s[r][1] = s[r][2] = s[r][3] = 0.f; }
#pragma unroll 4
        for (int d = 0; d < DQK; d++) {
            float4 kc = *(const float4*)&Kt[d * KTS + tx * 4];
            float a[8];
            *(float4*)(a)     = *(const float4*)&Qt[d * QTS + ty * 8];
            *(float4*)(a + 4) = *(const float4*)&Qt[d * QTS + ty * 8 + 4];
#pragma unroll
            for (int r = 0; r < 8; r++) {
                s[r][0] = fmaf(a[r], kc.x, s[r][0]);
                s[r][1] = fmaf(a[r], kc.y, s[r][1]);
                s[r][2] = fmaf(a[r], kc.z, s[r][2]);
                s[r][3] = fmaf(a[r], kc.w, s[r][3]);
            }
        }

        // Mask (skip entirely if tile is fully causal-allowed: k0+63 <= q0)
        if (k0 + SKt - 1 > q0) {
            bool gcol[4];
#pragma unroll
            for (int c = 0; c < 4; c++) {
                int k = k0 + tx * 4 + c;
                gcol[c] = (gbm[k >> 5] >> (k & 31)) & 1u;
            }
#pragma unroll
            for (int r = 0; r < 8; r++) {
                if (grow[r]) continue;
                int q = q0 + ty * 8 + r;
#pragma unroll
                for (int c = 0; c < 4; c++) {
                    int k = k0 + tx * 4 + c;
                    if (k > q && !gcol[c]) s[r][c] = NEG_INF;
                }
            }
        }

        // Online softmax update + write P (transposed)
#pragma unroll
        for (int r = 0; r < 8; r++) {
            float tm = fmaxf(fmaxf(s[r][0], s[r][1]), fmaxf(s[r][2], s[r][3]));
            tm = fmaxf(tm, __shfl_xor_sync(0xffffffffu, tm, 1, 16));
            tm = fmaxf(tm, __shfl_xor_sync(0xffffffffu, tm, 2, 16));
            tm = fmaxf(tm, __shfl_xor_sync(0xffffffffu, tm, 4, 16));
            tm = fmaxf(tm, __shfl_xor_sync(0xffffffffu, tm, 8, 16));
            float mn  = fmaxf(m_i[r], tm);
            float scl = __expf(m_i[r] - mn);   // m_i=-inf first time -> 0
            float p0 = __expf(s[r][0] - mn);
            float p1 = __expf(s[r][1] - mn);
            float p2 = __expf(s[r][2] - mn);
            float p3 = __expf(s[r][3] - mn);
            float rs = p0 + p1 + p2 + p3;
            rs += __shfl_xor_sync(0xffffffffu, rs, 1, 16);
            rs += __shfl_xor_sync(0xffffffffu, rs, 2, 16);
            rs += __shfl_xor_sync(0xffffffffu, rs, 4, 16);
            rs += __shfl_xor_sync(0xffffffffu, rs, 8, 16);
            l_i[r] = l_i[r] * scl + rs;
            m_i[r] = mn;
#pragma unroll
            for (int c = 0; c < 8; c++) o[r][c] *= scl;
            int rowi = ty * 8 + r;
            Pt[(tx * 4 + 0) * VS_ + rowi] = p0;
            Pt[(tx * 4 + 1) * VS_ + rowi] = p1;
            Pt[(tx * 4 + 2) * VS_ + rowi] = p2;
            Pt[(tx * 4 + 3) * VS_ + rowi] = p3;
        }
        __syncthreads();

        // O += P @ V
#pragma unroll 2
        for (int kk = 0; kk < SKt; kk++) {
            float p[8];
            *(float4*)(p)     = *(const float4*)&Pt[kk * VS_ + ty * 8];
            *(float4*)(p + 4) = *(const float4*)&Pt[kk * VS_ + ty * 8 + 4];
            float vv[8];
#pragma unroll
            for (int c = 0; c < 8; c++) vv[c] = Vs[kk * VS_ + c * 16 + tx];
#pragma unroll
            for (int r = 0; r < 8; r++)
#pragma unroll
                for (int c = 0; c < 8; c++)
                    o[r][c] = fmaf(p[r], vv[c], o[r][c]);
        }
    }

    // Normalize + store. O column of slot c is c*16 + tx.
#pragma unroll
    for (int r = 0; r < 8; r++) {
        float invl = 1.0f / l_i[r];
        float* op = Out + ((size_t)b * SEQ + q0 + ty * 8 + r) * DQK + tx;
#pragma unroll
        for (int c = 0; c < 8; c++) op[c * 16] = o[r][c] * invl;
    }
}

// ---------------------------------------------------------------------------
// Host: exact reproduction of np.random.default_rng(0).choice(2048, 32, False).
// numpy Generator.choice (p=None, replace=False, pop_size<=10000) uses
// FLOYD'S ALGORITHM with a linear-probe hash set (_generator.pyx), NOT
// permutation:
//   set_size = 1 + _gen_mask((uint64)(1.2*32)) = 64
//   for j in 2016..2047:
//     val = random_bounded_uint64(0, j, 0, use_masked=0)   // Lemire uint32
//     probe val&63; insert val if free, else insert j (probe from j&63)
// ---------------------------------------------------------------------------
typedef uint32_t u32; typedef uint64_t u64; typedef unsigned __int128 u128;

static void compute_gtok(int* out) {
    const u32 XSHIFT = 16;
    // --- SeedSequence(0), pool_size=4 ---
    u32 pool[4];
    u32 hash_const = 0x43b0d7e5u;  // INIT_A
    auto hashmix = [&](u32 value) -> u32 {
        value ^= hash_const;
        hash_const *= 0x931e8875u;  // MULT_A
        value *= hash_const;
        value ^= value >> XSHIFT;
        return value;
    };
    auto mixfn = [&](u32 x, u32 y) -> u32 {
        u32 r = x * 0xca01f9ddu - y * 0x4973f715u;  // MIX_MULT_L/_R
        r ^= r >> XSHIFT;
        return r;
    };
    // assembled entropy = [0]
    for (int i = 0; i < 4; i++) pool[i] = hashmix(0u);
    for (int s = 0; s < 4; s++)
        for (int d = 0; d < 4; d++)
            if (s != d) pool[d] = mixfn(pool[d], hashmix(pool[s]));

    // generate_state(4, uint64) -> 8 uint32 words, LE-paired to uint64
    u32 st32[8];
    u32 hc = 0x8b51f9ddu;  // INIT_B
    for (int i = 0; i < 8; i++) {
        u32 dv = pool[i % 4];
        dv ^= hc;
        hc *= 0x58f38dedu;  // MULT_B
        dv *= hc;
        dv ^= dv >> XSHIFT;
        st32[i] = dv;
    }
    u64 val[4];
    for (int i = 0; i < 4; i++)
        val[i] = (u64)st32[2 * i] | ((u64)st32[2 * i + 1] << 32);

    // --- PCG64 seeding: seed = (hi=val[0], lo=val[1]), incseed = (hi=val[2], lo=val[3]) ---
    const u128 MUL = ((u128)0x2360ed051fc65da4ULL << 64) | 0x4385df649fccf645ULL;
    u128 initstate = ((u128)val[0] << 64) | val[1];
    u128 initseq   = ((u128)val[2] << 64) | val[3];
    u128 state = 0;
    u128 inc = (initseq << 1) | 1;
    state = state * MUL + inc;   // step
    state += initstate;
    state = state * MUL + inc;   // step

    bool has32 = false; u32 cached = 0;
    auto next64 = [&]() -> u64 {
        state = state * MUL + inc;          // step first
        u64 hi = (u64)(state >> 64), lo = (u64)state;
        u64 x = hi ^ lo;                    // xsl-rr output of NEW state
        unsigned rot = (unsigned)(state >> 122);
        return (x >> rot) | (x << ((64u - rot) & 63u));
    };
    auto next32 = [&]() -> u32 {
        if (has32) { has32 = false; return cached; }
        u64 n = next64();
        has32 = true; cached = (u32)(n >> 32);  // cache high half
        return (u32)n;                          // return low half first
    };
    // buffered_bounded_lemire_uint32: uniform in [0, rng] inclusive
    auto lemire32 = [&](u32 rng) -> u32 {
        const u32 rng_excl = rng + 1u;
        u64 m = (u64)next32() * (u64)rng_excl;
        u32 leftover = (u32)m;
        if (leftover < rng_excl) {
            const u32 threshold = (u32)((0xffffffffu - rng) % rng_excl);
            while (leftover < threshold) {
                m = (u64)next32() * (u64)rng_excl;
                leftover = (u32)m;
            }
        }
        return (u32)(m >> 32);
    };

    // --- Floyd's algorithm with 64-slot linear-probe hash set ---
    const u64 EMPTY = ~(u64)0;
    u64 hash_set[64];
    for (int i = 0; i < 64; i++) hash_set[i] = EMPTY;
    int oi = 0;
    for (u32 j = SEQ - NG; j < SEQ; j++) {        // j = 2016..2047
        u64 v = (u64)lemire32(j);                  // val in [0, j]
        u64 loc = v & 63u;
        while (hash_set[loc] != EMPTY && hash_set[loc] != v) loc = (loc + 1) & 63u;
        if (hash_set[loc] == EMPTY) {
            hash_set[loc] = v;
            out[oi++] = (int)v;
        } else {
            loc = j & 63u;
            while (hash_set[loc] != EMPTY) loc = (loc + 1) & 63u;
            hash_set[loc] = j;
            out[oi++] = (int)j;
        }
    }
}

// ---------------------------------------------------------------------------
extern "C" void kernel_launch(void* const* d_in, const int* in_sizes, int n_in,
                              void* d_out, int out_size) {
    (void)in_sizes; (void)n_in; (void)out_size;
    InArgs ia;
    ia.X[0] = (const float*)d_in[0];   // q
    ia.X[1] = (const float*)d_in[1];   // k
    ia.X[2] = (const float*)d_in[2];   // v
    ia.W[0] = (const float*)d_in[3];  ia.B[0] = (const float*)d_in[4];  // Wq, bq
    ia.W[1] = (const float*)d_in[5];  ia.B[1] = (const float*)d_in[6];  // Wk, bk
    ia.W[2] = (const float*)d_in[7];  ia.B[2] = (const float*)d_in[8];  // Wv, bv

    GIdx gi;
    compute_gtok(gi.g);

    dim3 pg(BATCH * SEQ / 128, 3);
    proj_kernel<<<pg, 256>>>(ia);

    size_t smem = (size_t)(128 * QTS + 128 * KTS + SKt * VS_ + SKt * VS_) * sizeof(float);
    cudaFuncSetAttribute(attn_kernel, cudaFuncAttributeMaxDynamicSharedMemorySize, (int)smem);
    dim3 ag(SEQ / SQt, BATCH);
    attn_kernel<<<ag, 256, smem>>>((float*)d_out, gi);
}